// round 1
// baseline (speedup 1.0000x reference)
#include <cuda_runtime.h>

// Problem constants (fixed by the dataset)
#define BATCH 32
#define NA    3
#define GH    80
#define GW    80
#define NB    50
#define NCLS  1
#define HW    (GH*GW)                 // 6400
#define CELLS_PER_BATCH (NA*HW)       // 19200
#define THREADS 256
#define CHUNKS  (CELLS_PER_BATCH/THREADS) // 75

// Global accumulators: box, obj, noobj, cls, n_pos, sum_noobj
__device__ double g_acc[6];

__global__ void zero_acc_kernel() {
    int i = threadIdx.x;
    if (i < 6) g_acc[i] = 0.0;
}

__global__ __launch_bounds__(THREADS) void yolo_main_kernel(
    const float* __restrict__ head,
    const float* __restrict__ boxes,
    const float* __restrict__ anchors,
    const int*   __restrict__ labels)
{
    // Shared GT data for this batch
    __shared__ float4 s_cxyxy[NB];   // compacted xyxy for IoU-pruned list
    __shared__ float  s_caG[NB];     // compacted GT areas
    __shared__ int    s_cnt;
    __shared__ int    s_mn[NB];      // match-candidate gt index
    __shared__ int    s_mkey[NB];    // match-candidate cell key
    __shared__ int    s_mcnt;
    __shared__ float4 s_box[NB];     // (cx, cy, w, h) all gts
    __shared__ float4 s_xyxy[NB];    // xyxy all gts
    __shared__ int    s_lab[NB];
    __shared__ float  s_red[8][6];

    const int b       = blockIdx.y;
    const int chunk   = blockIdx.x;
    const int tid     = threadIdx.x;
    const int cellBase = chunk * THREADS;
    const int a       = cellBase / HW;          // 6400 % 256 == 0 -> constant per block
    const int rem0    = cellBase - a * HW;
    const int h0      = rem0 / GW;
    const int hLast   = (rem0 + THREADS - 1) / GW;

    if (tid == 0) { s_cnt = 0; s_mcnt = 0; }
    __syncthreads();

    // --- per-GT prep (threads 0..49) ---
    if (tid < NB) {
        const float4 g = ((const float4*)boxes)[b * NB + tid];
        const float cx = g.x, cy = g.y, w = g.z, h = g.w;
        const int gi = (int)floorf(cx * (float)GW);
        const int gj = (int)floorf(cy * (float)GH);
        const float aG = w * h;
        // anchor argmax (first max wins, matching jnp.argmax)
        int anc = 0; float best = -1.0f;
        #pragma unroll
        for (int k = 0; k < NA; k++) {
            const float aw = anchors[2*k], ah = anchors[2*k+1];
            const float it = fminf(w, aw) * fminf(h, ah);
            const float un = aG + aw * ah - it;
            const float r  = it / un;
            if (r > best) { best = r; anc = k; }
        }
        const float x1 = cx - 0.5f*w, y1 = cy - 0.5f*h;
        const float x2 = cx + 0.5f*w, y2 = cy + 0.5f*h;
        s_box[tid]  = g;
        s_xyxy[tid] = make_float4(x1, y1, x2, y2);
        s_lab[tid]  = labels[b * NB + tid];

        const int key = anc * HW + gj * GW + gi;
        if (key >= cellBase && key < cellBase + THREADS) {
            const int m = atomicAdd(&s_mcnt, 1);
            s_mn[m] = tid; s_mkey[m] = key;
        }
        // IoU prune: iou>0.5 requires pred center strictly inside gt box.
        // Block's by range: ((h0-0.1)/GH, (hLast+1.1)/GH). Keep gts whose
        // y-extent intersects it (with epsilon slack; prune is necessary-cond only).
        const float byLo = ((float)h0   - 0.1f) * (1.0f/GH) - 1e-4f;
        const float byHi = ((float)hLast + 1.1f) * (1.0f/GH) + 1e-4f;
        if (y1 < byHi && y2 > byLo) {
            const int m = atomicAdd(&s_cnt, 1);
            s_cxyxy[m] = make_float4(x1, y1, x2, y2);
            s_caG[m]   = aG;
        }
    }
    __syncthreads();

    // --- per-cell work ---
    const int cell = cellBase + tid;
    const int rem  = rem0 + tid;
    const int hy   = rem / GW;
    const int wx   = rem - hy * GW;
    const long base = ((long)(b * NA + a) * 6) * HW + rem;

    const float xObj = head[base];
    const float xCx  = head[base +     HW];
    const float xCy  = head[base + 2 * HW];
    const float xW   = head[base + 3 * HW];
    const float xH   = head[base + 4 * HW];
    const float xCls = head[base + 5 * HW];

    const float pObj = __fdividef(1.0f, 1.0f + __expf(-xObj));
    const float sx   = __fdividef(1.0f, 1.0f + __expf(-xCx));
    const float sy   = __fdividef(1.0f, 1.0f + __expf(-xCy));
    const float cx   = 1.2f * sx - 0.1f;
    const float cy   = 1.2f * sy - 0.1f;
    const float bx   = (cx + (float)wx) * (1.0f/GW);
    const float by   = (cy + (float)hy) * (1.0f/GH);
    const float aw   = anchors[2*a], ah = anchors[2*a+1];
    const float bw   = __expf(xW) * aw;
    const float bh   = __expf(xH) * ah;
    const float pCls = __fdividef(1.0f, 1.0f + __expf(-xCls));

    const float px1 = bx - 0.5f*bw, py1 = by - 0.5f*bh;
    const float px2 = bx + 0.5f*bw, py2 = by + 0.5f*bh;
    const float aP  = bw * bh;

    // noobj: any gt with iou > 0.5  <=>  3*inter > aG + aP
    bool ign = false;
    const int cnt = s_cnt;
    for (int i = 0; i < cnt; i++) {
        const float4 g = s_cxyxy[i];
        const float ox = fminf(px2, g.z) - fmaxf(px1, g.x);
        const float oy = fminf(py2, g.w) - fmaxf(py1, g.y);
        const float inter = fmaxf(ox, 0.0f) * fmaxf(oy, 0.0f);
        ign = ign || (3.0f * inter > s_caG[i] + aP);
    }
    const float noobj = ign ? 0.0f : 1.0f;

    // target match: last-write-wins == largest matching n
    int bestN = -1;
    const int mcnt = s_mcnt;
    for (int i = 0; i < mcnt; i++) {
        if (s_mkey[i] == cell && s_mn[i] > bestN) bestN = s_mn[i];
    }

    const float logP   = fmaxf(__logf(pObj),        -100.0f);
    const float log1mP = fmaxf(__logf(1.0f - pObj), -100.0f);

    float v0 = 0.0f, v1 = 0.0f, v2 = 0.0f, v3 = 0.0f, v4 = 0.0f;
    if (bestN >= 0) {
        v4 = 1.0f;               // n_pos
        v1 = -logP;              // obj_loss: bce(p, 1)
        v2 = noobj * (-logP);    // noobj_loss term at target cell (t=1)
        // cls bce
        const float t   = (s_lab[bestN] == 0) ? 1.0f : 0.0f;
        const float lc1 = fmaxf(__logf(pCls),        -100.0f);
        const float lc0 = fmaxf(__logf(1.0f - pCls), -100.0f);
        v3 = -(t * lc1 + (1.0f - t) * lc0);
        // ciou(pred, target)
        const float4 gb = s_box[bestN];
        const float4 gx = s_xyxy[bestN];
        const float imx = fmaxf(px1, gx.x), imy = fmaxf(py1, gx.y);
        const float iMx = fminf(px2, gx.z), iMy = fminf(py2, gx.w);
        const float iw = fmaxf(iMx - imx, 0.0f), ihh = fmaxf(iMy - imy, 0.0f);
        const float inter = iw * ihh;
        const float uni = bw * bh + gb.z * gb.w - inter;
        const float iou = inter / fmaxf(uni, 1e-6f);
        const float d   = fabsf(bx - gb.x) + fabsf(by - gb.y);
        const float ex1 = fminf(px1, gx.x), ey1 = fminf(py1, gx.y);
        const float ex2 = fmaxf(px2, gx.z), ey2 = fmaxf(py2, gx.w);
        const float cc  = fabsf(ex2 - ex1) + fabsf(ey2 - ey1);
        const float dis = d / fmaxf(cc, 1e-6f);
        const float a1  = atanf(bw / fmaxf(bh, 1e-6f));
        const float a2  = atanf(gb.z / fmaxf(gb.w, 1e-6f));
        const float PIc = 3.1415926f;
        const float vv  = (4.0f / (PIc * PIc)) * fabsf(a1 - a2);
        const float al  = vv / fmaxf(1.0f - iou + vv, 1e-6f);
        v0 = 1.0f - iou + dis + al * vv;
    } else {
        v2 = noobj * (-log1mP);  // bce(p, 0)
    }
    const float v5 = noobj;

    // --- block reduction ---
    float vals[6] = {v0, v1, v2, v3, v4, v5};
    #pragma unroll
    for (int off = 16; off > 0; off >>= 1) {
        #pragma unroll
        for (int j = 0; j < 6; j++)
            vals[j] += __shfl_down_sync(0xFFFFFFFFu, vals[j], off);
    }
    const int lane = tid & 31, warp = tid >> 5;
    if (lane == 0) {
        #pragma unroll
        for (int j = 0; j < 6; j++) s_red[warp][j] = vals[j];
    }
    __syncthreads();
    if (warp == 0) {
        float r[6];
        #pragma unroll
        for (int j = 0; j < 6; j++) r[j] = (lane < 8) ? s_red[lane][j] : 0.0f;
        #pragma unroll
        for (int off = 4; off > 0; off >>= 1) {
            #pragma unroll
            for (int j = 0; j < 6; j++)
                r[j] += __shfl_down_sync(0xFFFFFFFFu, r[j], off);
        }
        if (lane == 0) {
            #pragma unroll
            for (int j = 0; j < 6; j++) atomicAdd(&g_acc[j], (double)r[j]);
        }
    }
}

__global__ void finalize_kernel(float* __restrict__ out) {
    const double npos      = g_acc[4];
    const double box_loss  = 0.05 * g_acc[0] / npos;
    const double obj_l     = 1.5 * g_acc[1] + 0.5 * g_acc[2];
    const double cls_loss  = g_acc[3] / (npos * (double)NCLS);
    const double grid_loss = obj_l / (npos + g_acc[5]) + 0.5 * cls_loss;
    out[0] = (float)box_loss;
    out[1] = (float)grid_loss;
}

extern "C" void kernel_launch(void* const* d_in, const int* in_sizes, int n_in,
                              void* d_out, int out_size) {
    const float* head    = (const float*)d_in[0];
    const float* boxes   = (const float*)d_in[1];
    const float* anchors = (const float*)d_in[2];
    const int*   labels  = (const int*)d_in[3];
    (void)in_sizes; (void)n_in; (void)out_size;

    zero_acc_kernel<<<1, 32>>>();
    dim3 grid(CHUNKS, BATCH);
    yolo_main_kernel<<<grid, THREADS>>>(head, boxes, anchors, labels);
    finalize_kernel<<<1, 1>>>((float*)d_out);
}

// round 2
// speedup vs baseline: 1.1816x; 1.1816x over previous
#include <cuda_runtime.h>

// Problem constants (fixed by the dataset)
#define BATCH 32
#define NA    3
#define GH    80
#define GW    80
#define NB    50
#define NCLS  1
#define HW    (GH*GW)                 // 6400
#define THREADS 256

// 16x16 spatial tiles: 5x5 tiles per (batch, anchor)
#define TW 16
#define TH 16
#define TILES_X (GW/TW)               // 5
#define TILES_Y (GH/TH)               // 5
#define TILES   (TILES_X*TILES_Y)     // 25
#define BLOCKS_PER_B (NA*TILES)       // 75
#define TOTAL_BLOCKS (BATCH*BLOCKS_PER_B) // 2400

// Scratch: per-block partials (box, obj, noobj, cls, n_pos, sum_noobj) + counter
__device__ float g_part[TOTAL_BLOCKS][6];
__device__ int   g_count = 0;

__global__ __launch_bounds__(THREADS) void yolo_fused_kernel(
    const float* __restrict__ head,
    const float* __restrict__ boxes,
    const float* __restrict__ anchors,
    const int*   __restrict__ labels,
    float* __restrict__ out)
{
    __shared__ float4 s_cxyxy[NB];   // pruned GT xyxy for noobj test
    __shared__ float  s_caG[NB];     // pruned GT areas
    __shared__ int    s_cnt;
    __shared__ int    s_mn[NB];      // match-candidate gt index
    __shared__ int    s_mij[NB];     // match-candidate packed (gj<<8)|gi
    __shared__ int    s_mcnt;
    __shared__ float4 s_box[NB];     // (cx, cy, w, h) all gts
    __shared__ float4 s_xyxy[NB];    // xyxy all gts
    __shared__ int    s_lab[NB];
    __shared__ float  s_red[8][6];
    __shared__ double s_dred[8][6];
    __shared__ int    s_isLast;

    const int b    = blockIdx.y;
    const int blk  = blockIdx.x;                 // 0..74
    const int tid  = threadIdx.x;
    const int a    = blk / TILES;                // anchor
    const int t    = blk - a * TILES;
    const int th   = t / TILES_X;
    const int tw   = t - th * TILES_X;
    const int w0   = tw * TW;
    const int h0   = th * TH;

    if (tid == 0) { s_cnt = 0; s_mcnt = 0; s_isLast = 0; }
    __syncthreads();

    // --- per-GT prep (threads 0..49) ---
    if (tid < NB) {
        const float4 g = ((const float4*)boxes)[b * NB + tid];
        const float cx = g.x, cy = g.y, w = g.z, h = g.w;
        const int gi = (int)floorf(cx * (float)GW);
        const int gj = (int)floorf(cy * (float)GH);
        const float aG = w * h;
        // anchor argmax (first max wins, matching jnp.argmax)
        int anc = 0; float best = -1.0f;
        #pragma unroll
        for (int k = 0; k < NA; k++) {
            const float aw = anchors[2*k], ah = anchors[2*k+1];
            const float it = fminf(w, aw) * fminf(h, ah);
            const float un = aG + aw * ah - it;
            const float r  = it / un;
            if (r > best) { best = r; anc = k; }
        }
        const float x1 = cx - 0.5f*w, y1 = cy - 0.5f*h;
        const float x2 = cx + 0.5f*w, y2 = cy + 0.5f*h;
        s_box[tid]  = g;
        s_xyxy[tid] = make_float4(x1, y1, x2, y2);
        s_lab[tid]  = labels[b * NB + tid];

        if (anc == a && gi >= w0 && gi < w0 + TW && gj >= h0 && gj < h0 + TH) {
            const int m = atomicAdd(&s_mcnt, 1);
            s_mn[m] = tid; s_mij[m] = (gj << 8) | gi;
        }
        // noobj prune: iou>0.5 requires pred center strictly inside gt box.
        // Tile's bx range: ((w0-0.1)/GW, (w0+TW-1+1.1)/GW); same for by.
        const float bxLo = ((float)w0        - 0.1f) * (1.0f/GW) - 1e-4f;
        const float bxHi = ((float)(w0+TW-1) + 1.1f) * (1.0f/GW) + 1e-4f;
        const float byLo = ((float)h0        - 0.1f) * (1.0f/GH) - 1e-4f;
        const float byHi = ((float)(h0+TH-1) + 1.1f) * (1.0f/GH) + 1e-4f;
        if (x1 < bxHi && x2 > bxLo && y1 < byHi && y2 > byLo) {
            const int m = atomicAdd(&s_cnt, 1);
            s_cxyxy[m] = make_float4(x1, y1, x2, y2);
            s_caG[m]   = aG;
        }
    }
    __syncthreads();

    // --- per-cell work ---
    const int wx  = w0 + (tid & (TW-1));
    const int hy  = h0 + (tid >> 4);
    const int rem = hy * GW + wx;
    const long base = ((long)(b * NA + a) * 6) * HW + rem;

    const float xObj = head[base];
    const float xCx  = head[base +     HW];
    const float xCy  = head[base + 2 * HW];
    const float xW   = head[base + 3 * HW];
    const float xH   = head[base + 4 * HW];
    const float xCls = head[base + 5 * HW];

    const float pObj = __fdividef(1.0f, 1.0f + __expf(-xObj));
    const float sx   = __fdividef(1.0f, 1.0f + __expf(-xCx));
    const float sy   = __fdividef(1.0f, 1.0f + __expf(-xCy));
    const float cx   = 1.2f * sx - 0.1f;
    const float cy   = 1.2f * sy - 0.1f;
    const float bx   = (cx + (float)wx) * (1.0f/GW);
    const float by   = (cy + (float)hy) * (1.0f/GH);
    const float aw   = anchors[2*a], ah = anchors[2*a+1];
    const float bw   = __expf(xW) * aw;
    const float bh   = __expf(xH) * ah;
    const float pCls = __fdividef(1.0f, 1.0f + __expf(-xCls));

    const float px1 = bx - 0.5f*bw, py1 = by - 0.5f*bh;
    const float px2 = bx + 0.5f*bw, py2 = by + 0.5f*bh;
    const float aP  = bw * bh;

    // noobj: any gt with iou > 0.5  <=>  3*inter > aG + aP
    bool ign = false;
    const int cnt = s_cnt;
    for (int i = 0; i < cnt; i++) {
        const float4 g = s_cxyxy[i];
        const float ox = fminf(px2, g.z) - fmaxf(px1, g.x);
        const float oy = fminf(py2, g.w) - fmaxf(py1, g.y);
        const float inter = fmaxf(ox, 0.0f) * fmaxf(oy, 0.0f);
        ign = ign || (3.0f * inter > s_caG[i] + aP);
    }
    const float noobj = ign ? 0.0f : 1.0f;

    // target match: last-write-wins == largest matching n
    const int myij = (hy << 8) | wx;
    int bestN = -1;
    const int mcnt = s_mcnt;
    for (int i = 0; i < mcnt; i++) {
        if (s_mij[i] == myij && s_mn[i] > bestN) bestN = s_mn[i];
    }

    const float logP   = fmaxf(__logf(pObj),        -100.0f);
    const float log1mP = fmaxf(__logf(1.0f - pObj), -100.0f);

    float v0 = 0.0f, v1 = 0.0f, v2 = 0.0f, v3 = 0.0f, v4 = 0.0f;
    if (bestN >= 0) {
        v4 = 1.0f;               // n_pos
        v1 = -logP;              // obj_loss: bce(p, 1)
        v2 = noobj * (-logP);    // noobj_loss term at target cell (t=1)
        // cls bce
        const float tC  = (s_lab[bestN] == 0) ? 1.0f : 0.0f;
        const float lc1 = fmaxf(__logf(pCls),        -100.0f);
        const float lc0 = fmaxf(__logf(1.0f - pCls), -100.0f);
        v3 = -(tC * lc1 + (1.0f - tC) * lc0);
        // ciou(pred, target)
        const float4 gb = s_box[bestN];
        const float4 gx = s_xyxy[bestN];
        const float imx = fmaxf(px1, gx.x), imy = fmaxf(py1, gx.y);
        const float iMx = fminf(px2, gx.z), iMy = fminf(py2, gx.w);
        const float iw = fmaxf(iMx - imx, 0.0f), ihh = fmaxf(iMy - imy, 0.0f);
        const float inter = iw * ihh;
        const float uni = bw * bh + gb.z * gb.w - inter;
        const float iou = inter / fmaxf(uni, 1e-6f);
        const float d   = fabsf(bx - gb.x) + fabsf(by - gb.y);
        const float ex1 = fminf(px1, gx.x), ey1 = fminf(py1, gx.y);
        const float ex2 = fmaxf(px2, gx.z), ey2 = fmaxf(py2, gx.w);
        const float cc  = fabsf(ex2 - ex1) + fabsf(ey2 - ey1);
        const float dis = d / fmaxf(cc, 1e-6f);
        const float a1  = atanf(bw / fmaxf(bh, 1e-6f));
        const float a2  = atanf(gb.z / fmaxf(gb.w, 1e-6f));
        const float PIc = 3.1415926f;
        const float vv  = (4.0f / (PIc * PIc)) * fabsf(a1 - a2);
        const float al  = vv / fmaxf(1.0f - iou + vv, 1e-6f);
        v0 = 1.0f - iou + dis + al * vv;
    } else {
        v2 = noobj * (-log1mP);  // bce(p, 0)
    }
    const float v5 = noobj;

    // --- block reduction (6 channels) ---
    float vals[6] = {v0, v1, v2, v3, v4, v5};
    #pragma unroll
    for (int off = 16; off > 0; off >>= 1) {
        #pragma unroll
        for (int j = 0; j < 6; j++)
            vals[j] += __shfl_down_sync(0xFFFFFFFFu, vals[j], off);
    }
    const int lane = tid & 31, warp = tid >> 5;
    if (lane == 0) {
        #pragma unroll
        for (int j = 0; j < 6; j++) s_red[warp][j] = vals[j];
    }
    __syncthreads();
    const int bid = b * BLOCKS_PER_B + blk;
    if (warp == 0) {
        float r[6];
        #pragma unroll
        for (int j = 0; j < 6; j++) r[j] = (lane < 8) ? s_red[lane][j] : 0.0f;
        #pragma unroll
        for (int off = 4; off > 0; off >>= 1) {
            #pragma unroll
            for (int j = 0; j < 6; j++)
                r[j] += __shfl_down_sync(0xFFFFFFFFu, r[j], off);
        }
        if (lane == 0) {
            #pragma unroll
            for (int j = 0; j < 6; j++) g_part[bid][j] = r[j];
            __threadfence();
            const int old = atomicAdd(&g_count, 1);
            if (old == TOTAL_BLOCKS - 1) s_isLast = 1;
        }
    }
    __syncthreads();

    // --- last block: final reduction + output + counter reset ---
    if (s_isLast) {
        double acc[6] = {0.0, 0.0, 0.0, 0.0, 0.0, 0.0};
        for (int r = tid; r < TOTAL_BLOCKS; r += THREADS) {
            #pragma unroll
            for (int j = 0; j < 6; j++) acc[j] += (double)g_part[r][j];
        }
        #pragma unroll
        for (int off = 16; off > 0; off >>= 1) {
            #pragma unroll
            for (int j = 0; j < 6; j++)
                acc[j] += __shfl_down_sync(0xFFFFFFFFu, acc[j], off);
        }
        if (lane == 0) {
            #pragma unroll
            for (int j = 0; j < 6; j++) s_dred[warp][j] = acc[j];
        }
        __syncthreads();
        if (tid == 0) {
            double s[6];
            #pragma unroll
            for (int j = 0; j < 6; j++) {
                s[j] = 0.0;
                #pragma unroll
                for (int w = 0; w < 8; w++) s[j] += s_dred[w][j];
            }
            const double npos      = s[4];
            const double box_loss  = 0.05 * s[0] / npos;
            const double obj_l     = 1.5 * s[1] + 0.5 * s[2];
            const double cls_loss  = s[3] / (npos * (double)NCLS);
            const double grid_loss = obj_l / (npos + s[5]) + 0.5 * cls_loss;
            out[0] = (float)box_loss;
            out[1] = (float)grid_loss;
            g_count = 0;   // reset for next graph replay
        }
    }
}

extern "C" void kernel_launch(void* const* d_in, const int* in_sizes, int n_in,
                              void* d_out, int out_size) {
    const float* head    = (const float*)d_in[0];
    const float* boxes   = (const float*)d_in[1];
    const float* anchors = (const float*)d_in[2];
    const int*   labels  = (const int*)d_in[3];
    (void)in_sizes; (void)n_in; (void)out_size;

    dim3 grid(BLOCKS_PER_B, BATCH);
    yolo_fused_kernel<<<grid, THREADS>>>(head, boxes, anchors, labels, (float*)d_out);
}

// round 3
// speedup vs baseline: 1.4095x; 1.1929x over previous
#include <cuda_runtime.h>

// Problem constants (fixed by the dataset)
#define BATCH 32
#define NA    3
#define GH    80
#define GW    80
#define NB    50
#define NCLS  1
#define HW    (GH*GW)                 // 6400
#define THREADS 256

// 16x16 spatial tiles; one block = one tile x ALL 3 anchors (768 cells, 3/thread)
#define TW 16
#define TH 16
#define TILES_X (GW/TW)               // 5
#define TILES_Y (GH/TH)               // 5
#define TILES   (TILES_X*TILES_Y)     // 25
#define TOTAL_BLOCKS (BATCH*TILES)    // 800

// Scratch: per-block partials (box, obj, noobj, cls, n_pos, sum_noobj) + counter
__device__ float g_part[TOTAL_BLOCKS][6];
__device__ int   g_count = 0;

__global__ __launch_bounds__(THREADS) void yolo_fused_kernel(
    const float* __restrict__ head,
    const float* __restrict__ boxes,
    const float* __restrict__ anchors,
    const int*   __restrict__ labels,
    float* __restrict__ out)
{
    __shared__ float4 s_cxyxy[NB];   // pruned GT xyxy for noobj test
    __shared__ float  s_caG[NB];     // pruned GT areas
    __shared__ int    s_cnt;
    __shared__ int    s_mn[NB];      // match-candidate gt index
    __shared__ int    s_mkey[NB];    // match-candidate packed (anc<<16)|(gj<<8)|gi
    __shared__ int    s_mcnt;
    __shared__ float4 s_box[NB];     // (cx, cy, w, h) all gts
    __shared__ float4 s_xyxy[NB];    // xyxy all gts
    __shared__ int    s_lab[NB];
    __shared__ float  s_red[8][6];
    __shared__ double s_dred[8][6];
    __shared__ int    s_isLast;

    const int b    = blockIdx.y;
    const int t    = blockIdx.x;                 // 0..24 spatial tile
    const int tid  = threadIdx.x;
    const int th   = t / TILES_X;
    const int tw   = t - th * TILES_X;
    const int w0   = tw * TW;
    const int h0   = th * TH;

    if (tid == 0) { s_cnt = 0; s_mcnt = 0; s_isLast = 0; }
    __syncthreads();

    // --- per-GT prep (threads 0..49), once per spatial tile (all anchors) ---
    if (tid < NB) {
        const float4 g = ((const float4*)boxes)[b * NB + tid];
        const float cx = g.x, cy = g.y, w = g.z, h = g.w;
        const int gi = (int)floorf(cx * (float)GW);
        const int gj = (int)floorf(cy * (float)GH);
        const float aG = w * h;
        // anchor argmax (first max wins, matching jnp.argmax)
        int anc = 0; float best = -1.0f;
        #pragma unroll
        for (int k = 0; k < NA; k++) {
            const float aw = anchors[2*k], ah = anchors[2*k+1];
            const float it = fminf(w, aw) * fminf(h, ah);
            const float un = aG + aw * ah - it;
            const float r  = it / un;
            if (r > best) { best = r; anc = k; }
        }
        const float x1 = cx - 0.5f*w, y1 = cy - 0.5f*h;
        const float x2 = cx + 0.5f*w, y2 = cy + 0.5f*h;
        s_box[tid]  = g;
        s_xyxy[tid] = make_float4(x1, y1, x2, y2);
        s_lab[tid]  = labels[b * NB + tid];

        if (gi >= w0 && gi < w0 + TW && gj >= h0 && gj < h0 + TH) {
            const int m = atomicAdd(&s_mcnt, 1);
            s_mn[m] = tid; s_mkey[m] = (anc << 16) | (gj << 8) | gi;
        }
        // noobj prune: iou>0.5 requires pred center strictly inside gt box.
        const float bxLo = ((float)w0        - 0.1f) * (1.0f/GW) - 1e-4f;
        const float bxHi = ((float)(w0+TW-1) + 1.1f) * (1.0f/GW) + 1e-4f;
        const float byLo = ((float)h0        - 0.1f) * (1.0f/GH) - 1e-4f;
        const float byHi = ((float)(h0+TH-1) + 1.1f) * (1.0f/GH) + 1e-4f;
        if (x1 < bxHi && x2 > bxLo && y1 < byHi && y2 > byLo) {
            const int m = atomicAdd(&s_cnt, 1);
            s_cxyxy[m] = make_float4(x1, y1, x2, y2);
            s_caG[m]   = aG;
        }
    }
    __syncthreads();

    // --- per-cell work: this thread's spatial cell, all 3 anchors ---
    const int wx  = w0 + (tid & (TW-1));
    const int hy  = h0 + (tid >> 4);
    const int rem = hy * GW + wx;

    float bxv[NA], byv[NA], bwv[NA], bhv[NA];
    float px1v[NA], py1v[NA], px2v[NA], py2v[NA], aPv[NA];
    float xObjv[NA], xClsv[NA];

    #pragma unroll
    for (int a = 0; a < NA; a++) {
        const long base = ((long)(b * NA + a) * 6) * HW + rem;
        xObjv[a]        = head[base];
        const float xCx = head[base +     HW];
        const float xCy = head[base + 2 * HW];
        const float xW  = head[base + 3 * HW];
        const float xH  = head[base + 4 * HW];
        xClsv[a]        = head[base + 5 * HW];

        const float sx = __fdividef(1.0f, 1.0f + __expf(-xCx));
        const float sy = __fdividef(1.0f, 1.0f + __expf(-xCy));
        const float cx = 1.2f * sx - 0.1f;
        const float cy = 1.2f * sy - 0.1f;
        const float bx = (cx + (float)wx) * (1.0f/GW);
        const float by = (cy + (float)hy) * (1.0f/GH);
        const float bw = __expf(xW) * anchors[2*a];
        const float bh = __expf(xH) * anchors[2*a+1];
        bxv[a] = bx; byv[a] = by; bwv[a] = bw; bhv[a] = bh;
        px1v[a] = bx - 0.5f*bw; py1v[a] = by - 0.5f*bh;
        px2v[a] = bx + 0.5f*bw; py2v[a] = by + 0.5f*bh;
        aPv[a]  = bw * bh;
    }

    // noobj: any gt with iou > 0.5  <=>  3*inter > aG + aP (shared GT fetch, 3 preds)
    bool ign0 = false, ign1 = false, ign2 = false;
    const int cnt = s_cnt;
    for (int i = 0; i < cnt; i++) {
        const float4 g = s_cxyxy[i];
        const float aG = s_caG[i];
        {
            const float ox = fminf(px2v[0], g.z) - fmaxf(px1v[0], g.x);
            const float oy = fminf(py2v[0], g.w) - fmaxf(py1v[0], g.y);
            ign0 = ign0 || (3.0f * (fmaxf(ox,0.0f)*fmaxf(oy,0.0f)) > aG + aPv[0]);
        }
        {
            const float ox = fminf(px2v[1], g.z) - fmaxf(px1v[1], g.x);
            const float oy = fminf(py2v[1], g.w) - fmaxf(py1v[1], g.y);
            ign1 = ign1 || (3.0f * (fmaxf(ox,0.0f)*fmaxf(oy,0.0f)) > aG + aPv[1]);
        }
        {
            const float ox = fminf(px2v[2], g.z) - fmaxf(px1v[2], g.x);
            const float oy = fminf(py2v[2], g.w) - fmaxf(py1v[2], g.y);
            ign2 = ign2 || (3.0f * (fmaxf(ox,0.0f)*fmaxf(oy,0.0f)) > aG + aPv[2]);
        }
    }
    const bool ignv[NA] = {ign0, ign1, ign2};

    float vals[6] = {0.0f, 0.0f, 0.0f, 0.0f, 0.0f, 0.0f};
    const int mcnt = s_mcnt;
    const int ijkey = (hy << 8) | wx;

    #pragma unroll
    for (int a = 0; a < NA; a++) {
        const float noobj = ignv[a] ? 0.0f : 1.0f;

        // target match: last-write-wins == largest matching n
        const int mykey = (a << 16) | ijkey;
        int bestN = -1;
        for (int i = 0; i < mcnt; i++) {
            if (s_mkey[i] == mykey && s_mn[i] > bestN) bestN = s_mn[i];
        }

        // softplus identity: -log(sigmoid(x)) = log(1+e^-x); -log(1-sigmoid(x)) = x + log(1+e^-x)
        const float xo = xObjv[a];
        const float l  = __logf(1.0f + __expf(-xo));

        if (bestN >= 0) {
            vals[4] += 1.0f;                     // n_pos
            const float bceP1 = fminf(l, 100.0f);
            vals[1] += bceP1;                    // obj: bce(p,1)
            vals[2] += noobj * bceP1;            // noobj at target cell (t=1)
            // cls bce (lazy sigmoid)
            const float pCls = __fdividef(1.0f, 1.0f + __expf(-xClsv[a]));
            const float tC   = (s_lab[bestN] == 0) ? 1.0f : 0.0f;
            const float lc1  = fmaxf(__logf(pCls),        -100.0f);
            const float lc0  = fmaxf(__logf(1.0f - pCls), -100.0f);
            vals[3] += -(tC * lc1 + (1.0f - tC) * lc0);
            // ciou(pred, target)
            const float4 gb = s_box[bestN];
            const float4 gx = s_xyxy[bestN];
            const float bx = bxv[a], by = byv[a], bw = bwv[a], bh = bhv[a];
            const float imx = fmaxf(px1v[a], gx.x), imy = fmaxf(py1v[a], gx.y);
            const float iMx = fminf(px2v[a], gx.z), iMy = fminf(py2v[a], gx.w);
            const float iw = fmaxf(iMx - imx, 0.0f), ihh = fmaxf(iMy - imy, 0.0f);
            const float inter = iw * ihh;
            const float uni = bw * bh + gb.z * gb.w - inter;
            const float iou = inter / fmaxf(uni, 1e-6f);
            const float d   = fabsf(bx - gb.x) + fabsf(by - gb.y);
            const float ex1 = fminf(px1v[a], gx.x), ey1 = fminf(py1v[a], gx.y);
            const float ex2 = fmaxf(px2v[a], gx.z), ey2 = fmaxf(py2v[a], gx.w);
            const float cc  = fabsf(ex2 - ex1) + fabsf(ey2 - ey1);
            const float dis = d / fmaxf(cc, 1e-6f);
            const float a1  = atanf(bw / fmaxf(bh, 1e-6f));
            const float a2  = atanf(gb.z / fmaxf(gb.w, 1e-6f));
            const float PIc = 3.1415926f;
            const float vv  = (4.0f / (PIc * PIc)) * fabsf(a1 - a2);
            const float al  = vv / fmaxf(1.0f - iou + vv, 1e-6f);
            vals[0] += 1.0f - iou + dis + al * vv;
        } else {
            vals[2] += noobj * fminf(xo + l, 100.0f);   // bce(p,0)
        }
        vals[5] += noobj;
    }

    // --- block reduction (6 channels) ---
    #pragma unroll
    for (int off = 16; off > 0; off >>= 1) {
        #pragma unroll
        for (int j = 0; j < 6; j++)
            vals[j] += __shfl_down_sync(0xFFFFFFFFu, vals[j], off);
    }
    const int lane = tid & 31, warp = tid >> 5;
    if (lane == 0) {
        #pragma unroll
        for (int j = 0; j < 6; j++) s_red[warp][j] = vals[j];
    }
    __syncthreads();
    const int bid = b * TILES + t;
    if (warp == 0) {
        float r[6];
        #pragma unroll
        for (int j = 0; j < 6; j++) r[j] = (lane < 8) ? s_red[lane][j] : 0.0f;
        #pragma unroll
        for (int off = 4; off > 0; off >>= 1) {
            #pragma unroll
            for (int j = 0; j < 6; j++)
                r[j] += __shfl_down_sync(0xFFFFFFFFu, r[j], off);
        }
        if (lane == 0) {
            #pragma unroll
            for (int j = 0; j < 6; j++) g_part[bid][j] = r[j];
            __threadfence();
            const int old = atomicAdd(&g_count, 1);
            if (old == TOTAL_BLOCKS - 1) s_isLast = 1;
        }
    }
    __syncthreads();

    // --- last block: final reduction + output + counter reset ---
    if (s_isLast) {
        double acc[6] = {0.0, 0.0, 0.0, 0.0, 0.0, 0.0};
        for (int r = tid; r < TOTAL_BLOCKS; r += THREADS) {
            #pragma unroll
            for (int j = 0; j < 6; j++) acc[j] += (double)g_part[r][j];
        }
        #pragma unroll
        for (int off = 16; off > 0; off >>= 1) {
            #pragma unroll
            for (int j = 0; j < 6; j++)
                acc[j] += __shfl_down_sync(0xFFFFFFFFu, acc[j], off);
        }
        if (lane == 0) {
            #pragma unroll
            for (int j = 0; j < 6; j++) s_dred[warp][j] = acc[j];
        }
        __syncthreads();
        if (tid == 0) {
            double s[6];
            #pragma unroll
            for (int j = 0; j < 6; j++) {
                s[j] = 0.0;
                #pragma unroll
                for (int w = 0; w < 8; w++) s[j] += s_dred[w][j];
            }
            const double npos      = s[4];
            const double box_loss  = 0.05 * s[0] / npos;
            const double obj_l     = 1.5 * s[1] + 0.5 * s[2];
            const double cls_loss  = s[3] / (npos * (double)NCLS);
            const double grid_loss = obj_l / (npos + s[5]) + 0.5 * cls_loss;
            out[0] = (float)box_loss;
            out[1] = (float)grid_loss;
            g_count = 0;   // reset for next graph replay
        }
    }
}

extern "C" void kernel_launch(void* const* d_in, const int* in_sizes, int n_in,
                              void* d_out, int out_size) {
    const float* head    = (const float*)d_in[0];
    const float* boxes   = (const float*)d_in[1];
    const float* anchors = (const float*)d_in[2];
    const int*   labels  = (const int*)d_in[3];
    (void)in_sizes; (void)n_in; (void)out_size;

    dim3 grid(TILES, BATCH);
    yolo_fused_kernel<<<grid, THREADS>>>(head, boxes, anchors, labels, (float*)d_out);
}

// round 4
// speedup vs baseline: 1.4288x; 1.0137x over previous
#include <cuda_runtime.h>

// Problem constants (fixed by the dataset)
#define BATCH 32
#define NA    3
#define GH    80
#define GW    80
#define NB    50
#define NCLS  1
#define HW    (GH*GW)                 // 6400
#define THREADS 256

// 16x16 spatial tiles; one block = one tile x ALL 3 anchors (768 cells, 3/thread)
#define TW 16
#define TH 16
#define TILES_X (GW/TW)               // 5
#define TILES_Y (GH/TH)               // 5
#define TILES   (TILES_X*TILES_Y)     // 25
#define TOTAL_BLOCKS (BATCH*TILES)    // 800

// Scratch: per-block partials (box, obj, noobj, cls, n_pos, sum_noobj) + counter
__device__ float g_part[TOTAL_BLOCKS][6];
__device__ int   g_count = 0;

__global__ __launch_bounds__(THREADS, 5) void yolo_fused_kernel(
    const float* __restrict__ head,
    const float* __restrict__ boxes,
    const float* __restrict__ anchors,
    const int*   __restrict__ labels,
    float* __restrict__ out)
{
    __shared__ float4 s_cxyxy[NB];   // pruned GT xyxy for noobj test
    __shared__ float  s_caG[NB];     // pruned GT areas
    __shared__ int    s_cnt;
    __shared__ int    s_mn[NB];      // match-candidate gt index
    __shared__ int    s_mkey[NB];    // match-candidate packed (anc<<16)|(gj<<8)|gi
    __shared__ int    s_mcnt;
    __shared__ float4 s_box[NB];     // (cx, cy, w, h) all gts
    __shared__ float4 s_xyxy[NB];    // xyxy all gts
    __shared__ int    s_lab[NB];
    __shared__ float  s_red[8][6];
    __shared__ double s_dred[8][6];
    __shared__ int    s_isLast;
    __shared__ float  s_anc[2*NA];

    const int b    = blockIdx.y;
    const int t    = blockIdx.x;                 // 0..24 spatial tile
    const int tid  = threadIdx.x;
    const int th   = t / TILES_X;
    const int tw   = t - th * TILES_X;
    const int w0   = tw * TW;
    const int h0   = th * TH;

    if (tid == 0) { s_cnt = 0; s_mcnt = 0; s_isLast = 0; }
    if (tid < 2*NA) s_anc[tid] = anchors[tid];
    __syncthreads();

    // --- per-GT prep (threads 0..49), once per spatial tile (all anchors) ---
    if (tid < NB) {
        const float4 g = ((const float4*)boxes)[b * NB + tid];
        const float cx = g.x, cy = g.y, w = g.z, h = g.w;
        const int gi = (int)floorf(cx * (float)GW);
        const int gj = (int)floorf(cy * (float)GH);
        const float aG = w * h;
        // anchor argmax (first max wins, matching jnp.argmax)
        int anc = 0; float best = -1.0f;
        #pragma unroll
        for (int k = 0; k < NA; k++) {
            const float aw = s_anc[2*k], ah = s_anc[2*k+1];
            const float it = fminf(w, aw) * fminf(h, ah);
            const float un = aG + aw * ah - it;
            const float r  = it / un;
            if (r > best) { best = r; anc = k; }
        }
        const float x1 = cx - 0.5f*w, y1 = cy - 0.5f*h;
        const float x2 = cx + 0.5f*w, y2 = cy + 0.5f*h;
        s_box[tid]  = g;
        s_xyxy[tid] = make_float4(x1, y1, x2, y2);
        s_lab[tid]  = labels[b * NB + tid];

        if (gi >= w0 && gi < w0 + TW && gj >= h0 && gj < h0 + TH) {
            const int m = atomicAdd(&s_mcnt, 1);
            s_mn[m] = tid; s_mkey[m] = (anc << 16) | (gj << 8) | gi;
        }
        // noobj prune: iou>0.5 requires pred center strictly inside gt box.
        const float bxLo = ((float)w0        - 0.1f) * (1.0f/GW) - 1e-4f;
        const float bxHi = ((float)(w0+TW-1) + 1.1f) * (1.0f/GW) + 1e-4f;
        const float byLo = ((float)h0        - 0.1f) * (1.0f/GH) - 1e-4f;
        const float byHi = ((float)(h0+TH-1) + 1.1f) * (1.0f/GH) + 1e-4f;
        if (x1 < bxHi && x2 > bxLo && y1 < byHi && y2 > byLo) {
            const int m = atomicAdd(&s_cnt, 1);
            s_cxyxy[m] = make_float4(x1, y1, x2, y2);
            s_caG[m]   = aG;
        }
    }
    __syncthreads();

    // --- per-cell work: this thread's spatial cell, all 3 anchors ---
    const int wx  = w0 + (tid & (TW-1));
    const int hy  = h0 + (tid >> 4);
    const int rem = hy * GW + wx;

    // Load all 18 channels up front (high MLP), 32-bit addressing.
    float ch[NA][6];
    #pragma unroll
    for (int a = 0; a < NA; a++) {
        const int base = (b * NA + a) * (6 * HW) + rem;   // fits in int32
        #pragma unroll
        for (int c = 0; c < 6; c++) ch[a][c] = head[base + c * HW];
    }

    float vals[6] = {0.0f, 0.0f, 0.0f, 0.0f, 0.0f, 0.0f};
    const int cnt   = s_cnt;
    const int mcnt  = s_mcnt;
    const int ijkey = (hy << 8) | wx;

    #pragma unroll
    for (int a = 0; a < NA; a++) {
        // Decode this anchor's pred box
        const float sx = __fdividef(1.0f, 1.0f + __expf(-ch[a][1]));
        const float sy = __fdividef(1.0f, 1.0f + __expf(-ch[a][2]));
        const float bx = (1.2f * sx - 0.1f + (float)wx) * (1.0f/GW);
        const float by = (1.2f * sy - 0.1f + (float)hy) * (1.0f/GH);
        const float bw = __expf(ch[a][3]) * s_anc[2*a];
        const float bh = __expf(ch[a][4]) * s_anc[2*a+1];
        const float px1 = bx - 0.5f*bw, py1 = by - 0.5f*bh;
        const float px2 = bx + 0.5f*bw, py2 = by + 0.5f*bh;
        const float aP  = bw * bh;

        // noobj: any gt with iou > 0.5  <=>  3*inter > aG + aP
        bool ign = false;
        for (int i = 0; i < cnt; i++) {
            const float4 g = s_cxyxy[i];               // broadcast LDS
            const float ox = fminf(px2, g.z) - fmaxf(px1, g.x);
            const float oy = fminf(py2, g.w) - fmaxf(py1, g.y);
            ign = ign || (3.0f * (fmaxf(ox,0.0f)*fmaxf(oy,0.0f)) > s_caG[i] + aP);
        }
        const float noobj = ign ? 0.0f : 1.0f;

        // target match: last-write-wins == largest matching n
        const int mykey = (a << 16) | ijkey;
        int bestN = -1;
        for (int i = 0; i < mcnt; i++) {
            if (s_mkey[i] == mykey && s_mn[i] > bestN) bestN = s_mn[i];
        }

        // softplus identity: -log(sigmoid(x)) = log(1+e^-x); -log(1-sigmoid(x)) = x + softplus(-x)
        const float xo = ch[a][0];
        const float l  = __logf(1.0f + __expf(-xo));

        if (bestN >= 0) {
            vals[4] += 1.0f;                     // n_pos
            const float bceP1 = fminf(l, 100.0f);
            vals[1] += bceP1;                    // obj: bce(p,1)
            vals[2] += noobj * bceP1;            // noobj at target cell (t=1)
            // cls bce (lazy sigmoid)
            const float pCls = __fdividef(1.0f, 1.0f + __expf(-ch[a][5]));
            const float tC   = (s_lab[bestN] == 0) ? 1.0f : 0.0f;
            const float lc1  = fmaxf(__logf(pCls),        -100.0f);
            const float lc0  = fmaxf(__logf(1.0f - pCls), -100.0f);
            vals[3] += -(tC * lc1 + (1.0f - tC) * lc0);
            // ciou(pred, target)
            const float4 gb = s_box[bestN];
            const float4 gx = s_xyxy[bestN];
            const float imx = fmaxf(px1, gx.x), imy = fmaxf(py1, gx.y);
            const float iMx = fminf(px2, gx.z), iMy = fminf(py2, gx.w);
            const float iw = fmaxf(iMx - imx, 0.0f), ihh = fmaxf(iMy - imy, 0.0f);
            const float inter = iw * ihh;
            const float uni = bw * bh + gb.z * gb.w - inter;
            const float iou = inter / fmaxf(uni, 1e-6f);
            const float d   = fabsf(bx - gb.x) + fabsf(by - gb.y);
            const float ex1 = fminf(px1, gx.x), ey1 = fminf(py1, gx.y);
            const float ex2 = fmaxf(px2, gx.z), ey2 = fmaxf(py2, gx.w);
            const float cc  = fabsf(ex2 - ex1) + fabsf(ey2 - ey1);
            const float dis = d / fmaxf(cc, 1e-6f);
            const float a1  = atanf(bw / fmaxf(bh, 1e-6f));
            const float a2  = atanf(gb.z / fmaxf(gb.w, 1e-6f));
            const float PIc = 3.1415926f;
            const float vv  = (4.0f / (PIc * PIc)) * fabsf(a1 - a2);
            const float al  = vv / fmaxf(1.0f - iou + vv, 1e-6f);
            vals[0] += 1.0f - iou + dis + al * vv;
        } else {
            vals[2] += noobj * fminf(xo + l, 100.0f);   // bce(p,0)
        }
        vals[5] += noobj;
    }

    // --- block reduction (6 channels) ---
    #pragma unroll
    for (int off = 16; off > 0; off >>= 1) {
        #pragma unroll
        for (int j = 0; j < 6; j++)
            vals[j] += __shfl_down_sync(0xFFFFFFFFu, vals[j], off);
    }
    const int lane = tid & 31, warp = tid >> 5;
    if (lane == 0) {
        #pragma unroll
        for (int j = 0; j < 6; j++) s_red[warp][j] = vals[j];
    }
    __syncthreads();
    const int bid = b * TILES + t;
    if (warp == 0) {
        float r[6];
        #pragma unroll
        for (int j = 0; j < 6; j++) r[j] = (lane < 8) ? s_red[lane][j] : 0.0f;
        #pragma unroll
        for (int off = 4; off > 0; off >>= 1) {
            #pragma unroll
            for (int j = 0; j < 6; j++)
                r[j] += __shfl_down_sync(0xFFFFFFFFu, r[j], off);
        }
        if (lane == 0) {
            #pragma unroll
            for (int j = 0; j < 6; j++) g_part[bid][j] = r[j];
            __threadfence();
            const int old = atomicAdd(&g_count, 1);
            if (old == TOTAL_BLOCKS - 1) s_isLast = 1;
        }
    }
    __syncthreads();

    // --- last block: final reduction + output + counter reset ---
    if (s_isLast) {
        double acc[6] = {0.0, 0.0, 0.0, 0.0, 0.0, 0.0};
        for (int r = tid; r < TOTAL_BLOCKS; r += THREADS) {
            #pragma unroll
            for (int j = 0; j < 6; j++) acc[j] += (double)g_part[r][j];
        }
        #pragma unroll
        for (int off = 16; off > 0; off >>= 1) {
            #pragma unroll
            for (int j = 0; j < 6; j++)
                acc[j] += __shfl_down_sync(0xFFFFFFFFu, acc[j], off);
        }
        if (lane == 0) {
            #pragma unroll
            for (int j = 0; j < 6; j++) s_dred[warp][j] = acc[j];
        }
        __syncthreads();
        if (tid == 0) {
            double s[6];
            #pragma unroll
            for (int j = 0; j < 6; j++) {
                s[j] = 0.0;
                #pragma unroll
                for (int w = 0; w < 8; w++) s[j] += s_dred[w][j];
            }
            const double npos      = s[4];
            const double box_loss  = 0.05 * s[0] / npos;
            const double obj_l     = 1.5 * s[1] + 0.5 * s[2];
            const double cls_loss  = s[3] / (npos * (double)NCLS);
            const double grid_loss = obj_l / (npos + s[5]) + 0.5 * cls_loss;
            out[0] = (float)box_loss;
            out[1] = (float)grid_loss;
            g_count = 0;   // reset for next graph replay
        }
    }
}

extern "C" void kernel_launch(void* const* d_in, const int* in_sizes, int n_in,
                              void* d_out, int out_size) {
    const float* head    = (const float*)d_in[0];
    const float* boxes   = (const float*)d_in[1];
    const float* anchors = (const float*)d_in[2];
    const int*   labels  = (const int*)d_in[3];
    (void)in_sizes; (void)n_in; (void)out_size;

    dim3 grid(TILES, BATCH);
    yolo_fused_kernel<<<grid, THREADS>>>(head, boxes, anchors, labels, (float*)d_out);
}

// round 5
// speedup vs baseline: 1.5629x; 1.0938x over previous
#include <cuda_runtime.h>

// Problem constants (fixed by the dataset)
#define BATCH 32
#define NA    3
#define GH    80
#define GW    80
#define NB    50
#define NCLS  1
#define HW    (GH*GW)                 // 6400
#define THREADS 256

// 16x16 spatial tiles; one block = one tile x ALL 3 anchors (768 cells, 3/thread)
#define TW 16
#define TH 16
#define TILES_X (GW/TW)               // 5
#define TILES_Y (GH/TH)               // 5
#define TILES   (TILES_X*TILES_Y)     // 25
#define TOTAL_BLOCKS (BATCH*TILES)    // 800

// Scratch: per-block partials (box, obj, noobj, cls, n_pos, sum_noobj) + counter
__device__ float g_part[TOTAL_BLOCKS][6];
__device__ int   g_count = 0;

__global__ __launch_bounds__(THREADS, 6) void yolo_fused_kernel(
    const float* __restrict__ head,
    const float* __restrict__ boxes,
    const float* __restrict__ anchors,
    const int*   __restrict__ labels,
    float* __restrict__ out)
{
    __shared__ float4 s_cxyxy[64];   // pruned GT xyxy, two 32-wide segments
    __shared__ float  s_caG3[64];    // pruned GT area/3
    __shared__ int    s_pcnt[2];
    __shared__ int    s_mn[64];      // match-candidate gt index, segmented
    __shared__ int    s_mkey[64];    // packed (anc<<16)|(gj<<8)|gi
    __shared__ int    s_mcnt[2];
    __shared__ float4 s_box[NB];     // (cx, cy, w, h) all gts
    __shared__ float4 s_xyxy[NB];    // xyxy all gts
    __shared__ int    s_lab[NB];
    __shared__ float  s_red[8][6];
    __shared__ double s_dred[8][6];
    __shared__ int    s_isLast;

    const int b    = blockIdx.y;
    const int t    = blockIdx.x;                 // 0..24 spatial tile
    const int tid  = threadIdx.x;
    const int th   = t / TILES_X;
    const int tw   = t - th * TILES_X;
    const int w0   = tw * TW;
    const int h0   = th * TH;
    const int lane = tid & 31, warp = tid >> 5;

    if (tid == 0) s_isLast = 0;

    // --- per-GT prep: warps 0-1, ballot compaction, no atomics, no init barrier ---
    if (tid < 64) {
        const bool valid = tid < NB;
        float4 g = valid ? ((const float4*)boxes)[b * NB + tid]
                         : make_float4(4.0f, 4.0f, 0.0f, 0.0f);
        const float cx = g.x, cy = g.y, w = g.z, h = g.w;
        const int gi = (int)floorf(cx * (float)GW);
        const int gj = (int)floorf(cy * (float)GH);
        const float aG = w * h;
        // anchor argmax (first max wins, matching jnp.argmax)
        int anc = 0; float best = -1.0f;
        #pragma unroll
        for (int k = 0; k < NA; k++) {
            const float aw = anchors[2*k], ah = anchors[2*k+1];
            const float it = fminf(w, aw) * fminf(h, ah);
            const float un = aG + aw * ah - it;
            const float r  = it / un;
            if (r > best) { best = r; anc = k; }
        }
        const float x1 = cx - 0.5f*w, y1 = cy - 0.5f*h;
        const float x2 = cx + 0.5f*w, y2 = cy + 0.5f*h;
        if (valid) {
            s_box[tid]  = g;
            s_xyxy[tid] = make_float4(x1, y1, x2, y2);
            s_lab[tid]  = labels[b * NB + tid];
        }
        // match candidates (segment = warp)
        const bool mpred = valid && gi >= w0 && gi < w0 + TW && gj >= h0 && gj < h0 + TH;
        const unsigned mb = __ballot_sync(0xFFFFFFFFu, mpred);
        if (mpred) {
            const int pos = warp * 32 + __popc(mb & ((1u << lane) - 1u));
            s_mn[pos]   = tid;
            s_mkey[pos] = (anc << 16) | (gj << 8) | gi;
        }
        if (lane == 0) s_mcnt[warp] = __popc(mb);
        // noobj prune: iou>0.5 requires pred center strictly inside gt box.
        const float bxLo = ((float)w0        - 0.1f) * (1.0f/GW) - 1e-4f;
        const float bxHi = ((float)(w0+TW-1) + 1.1f) * (1.0f/GW) + 1e-4f;
        const float byLo = ((float)h0        - 0.1f) * (1.0f/GH) - 1e-4f;
        const float byHi = ((float)(h0+TH-1) + 1.1f) * (1.0f/GH) + 1e-4f;
        const bool ppred = valid && x1 < bxHi && x2 > bxLo && y1 < byHi && y2 > byLo;
        const unsigned pb = __ballot_sync(0xFFFFFFFFu, ppred);
        if (ppred) {
            const int pos = warp * 32 + __popc(pb & ((1u << lane) - 1u));
            s_cxyxy[pos] = make_float4(x1, y1, x2, y2);
            s_caG3[pos]  = aG * (1.0f/3.0f);
        }
        if (lane == 0) s_pcnt[warp] = __popc(pb);
    }

    // --- decode pred boxes (all threads, overlaps with GT prep on warps 2-7) ---
    const int wx   = w0 + (tid & (TW-1));
    const int hy   = h0 + (tid >> 4);
    const int rem  = hy * GW + wx;
    const int base0 = (b * NA) * (6 * HW) + rem;     // fits in int32

    float px1[NA], py1[NA], px2[NA], py2[NA], aP3[NA], xo[NA];
    #pragma unroll
    for (int a = 0; a < NA; a++) {
        const int base = base0 + a * (6 * HW);
        xo[a]           = head[base];
        const float xCx = head[base +     HW];
        const float xCy = head[base + 2 * HW];
        const float xW  = head[base + 3 * HW];
        const float xH  = head[base + 4 * HW];
        const float sx = __fdividef(1.0f, 1.0f + __expf(-xCx));
        const float sy = __fdividef(1.0f, 1.0f + __expf(-xCy));
        const float bx = (1.2f * sx - 0.1f + (float)wx) * (1.0f/GW);
        const float by = (1.2f * sy - 0.1f + (float)hy) * (1.0f/GH);
        const float bw = __expf(xW) * anchors[2*a];
        const float bh = __expf(xH) * anchors[2*a+1];
        px1[a] = bx - 0.5f*bw; py1[a] = by - 0.5f*bh;
        px2[a] = bx + 0.5f*bw; py2[a] = by + 0.5f*bh;
        aP3[a] = bw * bh * (1.0f/3.0f);
    }
    __syncthreads();

    // --- noobj scan: GT outer, anchors inner, warp-uniform y refinement ---
    // This warp covers grid rows [wrow, wrow+1] -> by in ((wrow-0.1)/GH, (wrow+1+1.1)/GH)
    const int   wrow = h0 + ((tid >> 5) << 1);
    const float wyLo = ((float)wrow        - 0.1f) * (1.0f/GH) - 1e-4f;
    const float wyHi = ((float)(wrow + 1)  + 1.1f) * (1.0f/GH) + 1e-4f;
    bool ign[NA] = {false, false, false};
    #pragma unroll
    for (int s = 0; s < 2; s++) {
        const int c = s_pcnt[s];
        for (int k = 0; k < c; k++) {
            const float4 g = s_cxyxy[s*32 + k];          // broadcast LDS
            if (g.y < wyHi && g.w > wyLo) {              // warp-uniform branch
                const float aG3 = s_caG3[s*32 + k];
                #pragma unroll
                for (int a = 0; a < NA; a++) {
                    const float ox = fminf(px2[a], g.z) - fmaxf(px1[a], g.x);
                    const float oy = fminf(py2[a], g.w) - fmaxf(py1[a], g.y);
                    ign[a] = ign[a] ||
                        (fmaxf(ox, 0.0f) * fmaxf(oy, 0.0f) > aG3 + aP3[a]);
                }
            }
        }
    }

    // --- per-anchor accumulation ---
    float vals[6] = {0.0f, 0.0f, 0.0f, 0.0f, 0.0f, 0.0f};
    const int ijkey = (hy << 8) | wx;
    #pragma unroll
    for (int a = 0; a < NA; a++) {
        const float noobj = ign[a] ? 0.0f : 1.0f;

        // target match: last-write-wins == largest matching n
        const int mykey = (a << 16) | ijkey;
        int bestN = -1;
        #pragma unroll
        for (int s = 0; s < 2; s++) {
            const int c = s_mcnt[s];
            for (int k = 0; k < c; k++) {
                const int i = s*32 + k;
                if (s_mkey[i] == mykey && s_mn[i] > bestN) bestN = s_mn[i];
            }
        }

        // softplus: -log(sigmoid(x)) = log(1+e^-x); -log(1-sigmoid(x)) = x + log(1+e^-x)
        const float l = __logf(1.0f + __expf(-xo[a]));

        if (bestN >= 0) {
            vals[4] += 1.0f;                     // n_pos
            const float bceP1 = fminf(l, 100.0f);
            vals[1] += bceP1;                    // obj: bce(p,1)
            vals[2] += noobj * bceP1;            // noobj at target cell (t=1)
            // cls bce (lazy load + lazy sigmoid)
            const float xCls = head[base0 + a * (6 * HW) + 5 * HW];
            const float pCls = __fdividef(1.0f, 1.0f + __expf(-xCls));
            const float tC   = (s_lab[bestN] == 0) ? 1.0f : 0.0f;
            const float lc1  = fmaxf(__logf(pCls),        -100.0f);
            const float lc0  = fmaxf(__logf(1.0f - pCls), -100.0f);
            vals[3] += -(tC * lc1 + (1.0f - tC) * lc0);
            // ciou(pred, target); recover bx,by,bw,bh from extents
            const float bw = px2[a] - px1[a], bh = py2[a] - py1[a];
            const float bx = 0.5f * (px1[a] + px2[a]);
            const float by = 0.5f * (py1[a] + py2[a]);
            const float4 gb = s_box[bestN];
            const float4 gx = s_xyxy[bestN];
            const float imx = fmaxf(px1[a], gx.x), imy = fmaxf(py1[a], gx.y);
            const float iMx = fminf(px2[a], gx.z), iMy = fminf(py2[a], gx.w);
            const float iw = fmaxf(iMx - imx, 0.0f), ihh = fmaxf(iMy - imy, 0.0f);
            const float inter = iw * ihh;
            const float uni = bw * bh + gb.z * gb.w - inter;
            const float iou = inter / fmaxf(uni, 1e-6f);
            const float d   = fabsf(bx - gb.x) + fabsf(by - gb.y);
            const float ex1 = fminf(px1[a], gx.x), ey1 = fminf(py1[a], gx.y);
            const float ex2 = fmaxf(px2[a], gx.z), ey2 = fmaxf(py2[a], gx.w);
            const float cc  = fabsf(ex2 - ex1) + fabsf(ey2 - ey1);
            const float dis = d / fmaxf(cc, 1e-6f);
            const float a1  = atanf(bw / fmaxf(bh, 1e-6f));
            const float a2  = atanf(gb.z / fmaxf(gb.w, 1e-6f));
            const float PIc = 3.1415926f;
            const float vv  = (4.0f / (PIc * PIc)) * fabsf(a1 - a2);
            const float al  = vv / fmaxf(1.0f - iou + vv, 1e-6f);
            vals[0] += 1.0f - iou + dis + al * vv;
        } else {
            vals[2] += noobj * fminf(xo[a] + l, 100.0f);   // bce(p,0)
        }
        vals[5] += noobj;
    }

    // --- block reduction (6 channels) ---
    #pragma unroll
    for (int off = 16; off > 0; off >>= 1) {
        #pragma unroll
        for (int j = 0; j < 6; j++)
            vals[j] += __shfl_down_sync(0xFFFFFFFFu, vals[j], off);
    }
    if (lane == 0) {
        #pragma unroll
        for (int j = 0; j < 6; j++) s_red[warp][j] = vals[j];
    }
    __syncthreads();
    const int bid = b * TILES + t;
    if (warp == 0) {
        float r[6];
        #pragma unroll
        for (int j = 0; j < 6; j++) r[j] = (lane < 8) ? s_red[lane][j] : 0.0f;
        #pragma unroll
        for (int off = 4; off > 0; off >>= 1) {
            #pragma unroll
            for (int j = 0; j < 6; j++)
                r[j] += __shfl_down_sync(0xFFFFFFFFu, r[j], off);
        }
        if (lane == 0) {
            #pragma unroll
            for (int j = 0; j < 6; j++) g_part[bid][j] = r[j];
            __threadfence();
            const int old = atomicAdd(&g_count, 1);
            if (old == TOTAL_BLOCKS - 1) s_isLast = 1;
        }
    }
    __syncthreads();

    // --- last block: final reduction + output + counter reset ---
    if (s_isLast) {
        double acc[6] = {0.0, 0.0, 0.0, 0.0, 0.0, 0.0};
        for (int r = tid; r < TOTAL_BLOCKS; r += THREADS) {
            #pragma unroll
            for (int j = 0; j < 6; j++) acc[j] += (double)g_part[r][j];
        }
        #pragma unroll
        for (int off = 16; off > 0; off >>= 1) {
            #pragma unroll
            for (int j = 0; j < 6; j++)
                acc[j] += __shfl_down_sync(0xFFFFFFFFu, acc[j], off);
        }
        if (lane == 0) {
            #pragma unroll
            for (int j = 0; j < 6; j++) s_dred[warp][j] = acc[j];
        }
        __syncthreads();
        if (tid == 0) {
            double s[6];
            #pragma unroll
            for (int j = 0; j < 6; j++) {
                s[j] = 0.0;
                #pragma unroll
                for (int w = 0; w < 8; w++) s[j] += s_dred[w][j];
            }
            const double npos      = s[4];
            const double box_loss  = 0.05 * s[0] / npos;
            const double obj_l     = 1.5 * s[1] + 0.5 * s[2];
            const double cls_loss  = s[3] / (npos * (double)NCLS);
            const double grid_loss = obj_l / (npos + s[5]) + 0.5 * cls_loss;
            out[0] = (float)box_loss;
            out[1] = (float)grid_loss;
            g_count = 0;   // reset for next graph replay
        }
    }
}

extern "C" void kernel_launch(void* const* d_in, const int* in_sizes, int n_in,
                              void* d_out, int out_size) {
    const float* head    = (const float*)d_in[0];
    const float* boxes   = (const float*)d_in[1];
    const float* anchors = (const float*)d_in[2];
    const int*   labels  = (const int*)d_in[3];
    (void)in_sizes; (void)n_in; (void)out_size;

    dim3 grid(TILES, BATCH);
    yolo_fused_kernel<<<grid, THREADS>>>(head, boxes, anchors, labels, (float*)d_out);
}

// round 6
// speedup vs baseline: 1.6175x; 1.0350x over previous
#include <cuda_runtime.h>

// Problem constants (fixed by the dataset)
#define BATCH 32
#define NA    3
#define GH    80
#define GW    80
#define NB    50
#define NCLS  1
#define HW    (GH*GW)                 // 6400
#define THREADS 256

// 16x16 spatial tiles; one block = one tile x ALL 3 anchors (768 cells, 3/thread)
#define TW 16
#define TH 16
#define TILES_X (GW/TW)               // 5
#define TILES_Y (GH/TH)               // 5
#define TILES   (TILES_X*TILES_Y)     // 25
#define TOTAL_BLOCKS (BATCH*TILES)    // 800

// Global accumulators: box, weighted_obj, cls, n_pos, noobj_cnt
__device__ double g_acc[5] = {0.0, 0.0, 0.0, 0.0, 0.0};
__device__ int    g_count  = 0;

__global__ __launch_bounds__(THREADS, 6) void yolo_fused_kernel(
    const float* __restrict__ head,
    const float* __restrict__ boxes,
    const float* __restrict__ anchors,
    const int*   __restrict__ labels,
    float* __restrict__ out)
{
    __shared__ float4 s_cxyxy[64];   // pruned GT xyxy, two 32-wide segments
    __shared__ float  s_caG3[64];    // pruned GT area/3
    __shared__ int    s_pcnt[2];
    __shared__ int    s_mpk[64];     // match candidate packed (anc<<22)|(gj<<14)|(gi<<6)|n
    __shared__ int    s_mcnt[2];
    __shared__ float4 s_box[NB];     // (cx, cy, w, h) all gts
    __shared__ float4 s_xyxy[NB];    // xyxy all gts
    __shared__ int    s_lab[NB];
    __shared__ float  s_red[8][5];
    __shared__ int    s_isLast;

    const int b    = blockIdx.y;
    const int t    = blockIdx.x;                 // 0..24 spatial tile
    const int tid  = threadIdx.x;
    const int th   = t / TILES_X;
    const int tw   = t - th * TILES_X;
    const int w0   = tw * TW;
    const int h0   = th * TH;
    const int lane = tid & 31, warp = tid >> 5;

    if (tid == 0) s_isLast = 0;

    // --- per-GT prep: warps 0-1, ballot compaction, no atomics ---
    if (tid < 64) {
        const bool valid = tid < NB;
        float4 g = valid ? ((const float4*)boxes)[b * NB + tid]
                         : make_float4(4.0f, 4.0f, 0.0f, 0.0f);
        const float cx = g.x, cy = g.y, w = g.z, h = g.w;
        const int gi = (int)floorf(cx * (float)GW);
        const int gj = (int)floorf(cy * (float)GH);
        const float aG = w * h;
        // anchor argmax (first max wins, matching jnp.argmax)
        int anc = 0; float best = -1.0f;
        #pragma unroll
        for (int k = 0; k < NA; k++) {
            const float aw = anchors[2*k], ah = anchors[2*k+1];
            const float it = fminf(w, aw) * fminf(h, ah);
            const float un = aG + aw * ah - it;
            const float r  = it / un;
            if (r > best) { best = r; anc = k; }
        }
        const float x1 = cx - 0.5f*w, y1 = cy - 0.5f*h;
        const float x2 = cx + 0.5f*w, y2 = cy + 0.5f*h;
        if (valid) {
            s_box[tid]  = g;
            s_xyxy[tid] = make_float4(x1, y1, x2, y2);
            s_lab[tid]  = labels[b * NB + tid];
        }
        // match candidates (segment = warp), packed single word
        const bool mpred = valid && gi >= w0 && gi < w0 + TW && gj >= h0 && gj < h0 + TH;
        const unsigned mb = __ballot_sync(0xFFFFFFFFu, mpred);
        if (mpred) {
            const int pos = warp * 32 + __popc(mb & ((1u << lane) - 1u));
            s_mpk[pos] = (anc << 22) | (gj << 14) | (gi << 6) | tid;
        }
        if (lane == 0) s_mcnt[warp] = __popc(mb);
        // noobj prune: iou>0.5 requires pred center strictly inside gt box.
        const float bxLo = ((float)w0        - 0.1f) * (1.0f/GW) - 1e-4f;
        const float bxHi = ((float)(w0+TW-1) + 1.1f) * (1.0f/GW) + 1e-4f;
        const float byLo = ((float)h0        - 0.1f) * (1.0f/GH) - 1e-4f;
        const float byHi = ((float)(h0+TH-1) + 1.1f) * (1.0f/GH) + 1e-4f;
        const bool ppred = valid && x1 < bxHi && x2 > bxLo && y1 < byHi && y2 > byLo;
        const unsigned pb = __ballot_sync(0xFFFFFFFFu, ppred);
        if (ppred) {
            const int pos = warp * 32 + __popc(pb & ((1u << lane) - 1u));
            s_cxyxy[pos] = make_float4(x1, y1, x2, y2);
            s_caG3[pos]  = aG * (1.0f/3.0f);
        }
        if (lane == 0) s_pcnt[warp] = __popc(pb);
    }

    // --- decode pred boxes (all threads, overlaps with GT prep on warps 2-7) ---
    const int wx   = w0 + (tid & (TW-1));
    const int hy   = h0 + (tid >> 4);
    const int rem  = hy * GW + wx;
    const int base0 = (b * NA) * (6 * HW) + rem;     // fits in int32

    float px1[NA], py1[NA], px2[NA], py2[NA], aP3[NA], xo[NA];
    #pragma unroll
    for (int a = 0; a < NA; a++) {
        const int base = base0 + a * (6 * HW);
        xo[a]           = head[base];
        const float xCx = head[base +     HW];
        const float xCy = head[base + 2 * HW];
        const float xW  = head[base + 3 * HW];
        const float xH  = head[base + 4 * HW];
        const float sx = __fdividef(1.0f, 1.0f + __expf(-xCx));
        const float sy = __fdividef(1.0f, 1.0f + __expf(-xCy));
        const float bx = (1.2f * sx - 0.1f + (float)wx) * (1.0f/GW);
        const float by = (1.2f * sy - 0.1f + (float)hy) * (1.0f/GH);
        const float bw = __expf(xW) * anchors[2*a];
        const float bh = __expf(xH) * anchors[2*a+1];
        px1[a] = bx - 0.5f*bw; py1[a] = by - 0.5f*bh;
        px2[a] = bx + 0.5f*bw; py2[a] = by + 0.5f*bh;
        aP3[a] = bw * bh * (1.0f/3.0f);
    }
    __syncthreads();

    // --- noobj scan: GT outer, anchors inner, warp-uniform y refinement ---
    const int   wrow = h0 + ((tid >> 5) << 1);
    const float wyLo = ((float)wrow        - 0.1f) * (1.0f/GH) - 1e-4f;
    const float wyHi = ((float)(wrow + 1)  + 1.1f) * (1.0f/GH) + 1e-4f;
    bool ign[NA] = {false, false, false};
    #pragma unroll
    for (int s = 0; s < 2; s++) {
        const int c = s_pcnt[s];
        for (int k = 0; k < c; k++) {
            const float4 g = s_cxyxy[s*32 + k];          // broadcast LDS
            if (g.y < wyHi && g.w > wyLo) {              // warp-uniform branch
                const float aG3 = s_caG3[s*32 + k];
                #pragma unroll
                for (int a = 0; a < NA; a++) {
                    const float ox = fminf(px2[a], g.z) - fmaxf(px1[a], g.x);
                    const float oy = fminf(py2[a], g.w) - fmaxf(py1[a], g.y);
                    ign[a] = ign[a] ||
                        (fmaxf(ox, 0.0f) * fmaxf(oy, 0.0f) > aG3 + aP3[a]);
                }
            }
        }
    }

    // --- per-anchor accumulation (5 pre-weighted channels) ---
    // c0=box, c1=1.5*obj+0.5*noobj_bce, c2=cls, c3=n_pos, c4=noobj_cnt
    float vals[5] = {0.0f, 0.0f, 0.0f, 0.0f, 0.0f};
    const int ijkey = (hy << 14) | (wx << 6);
    #pragma unroll
    for (int a = 0; a < NA; a++) {
        const float noobj = ign[a] ? 0.0f : 1.0f;

        // target match: last-write-wins == largest matching n (packed scan)
        const int myhi = (a << 22) | ijkey;   // upper bits to compare
        int bestN = -1;
        #pragma unroll
        for (int s = 0; s < 2; s++) {
            const int c = s_mcnt[s];
            for (int k = 0; k < c; k++) {
                const int pk = s_mpk[s*32 + k];
                if ((pk & ~63) == myhi) bestN = max(bestN, pk & 63);
            }
        }

        // softplus: -log(sigmoid(x)) = log(1+e^-x); -log(1-sigmoid(x)) = x + log(1+e^-x)
        const float l = __logf(1.0f + __expf(-xo[a]));

        if (bestN >= 0) {
            vals[3] += 1.0f;                     // n_pos
            const float bceP1 = fminf(l, 100.0f);
            vals[1] += 1.5f * bceP1 + 0.5f * noobj * bceP1;
            // cls bce (lazy load + lazy sigmoid)
            const float xCls = head[base0 + a * (6 * HW) + 5 * HW];
            const float pCls = __fdividef(1.0f, 1.0f + __expf(-xCls));
            const float tC   = (s_lab[bestN] == 0) ? 1.0f : 0.0f;
            const float lc1  = fmaxf(__logf(pCls),        -100.0f);
            const float lc0  = fmaxf(__logf(1.0f - pCls), -100.0f);
            vals[2] += -(tC * lc1 + (1.0f - tC) * lc0);
            // ciou(pred, target); recover bx,by,bw,bh from extents
            const float bw = px2[a] - px1[a], bh = py2[a] - py1[a];
            const float bx = 0.5f * (px1[a] + px2[a]);
            const float by = 0.5f * (py1[a] + py2[a]);
            const float4 gb = s_box[bestN];
            const float4 gx = s_xyxy[bestN];
            const float imx = fmaxf(px1[a], gx.x), imy = fmaxf(py1[a], gx.y);
            const float iMx = fminf(px2[a], gx.z), iMy = fminf(py2[a], gx.w);
            const float iw = fmaxf(iMx - imx, 0.0f), ihh = fmaxf(iMy - imy, 0.0f);
            const float inter = iw * ihh;
            const float uni = bw * bh + gb.z * gb.w - inter;
            const float iou = inter / fmaxf(uni, 1e-6f);
            const float d   = fabsf(bx - gb.x) + fabsf(by - gb.y);
            const float ex1 = fminf(px1[a], gx.x), ey1 = fminf(py1[a], gx.y);
            const float ex2 = fmaxf(px2[a], gx.z), ey2 = fmaxf(py2[a], gx.w);
            const float cc  = fabsf(ex2 - ex1) + fabsf(ey2 - ey1);
            const float dis = d / fmaxf(cc, 1e-6f);
            const float a1  = atanf(bw / fmaxf(bh, 1e-6f));
            const float a2  = atanf(gb.z / fmaxf(gb.w, 1e-6f));
            const float PIc = 3.1415926f;
            const float vv  = (4.0f / (PIc * PIc)) * fabsf(a1 - a2);
            const float al  = vv / fmaxf(1.0f - iou + vv, 1e-6f);
            vals[0] += 1.0f - iou + dis + al * vv;
        } else {
            vals[1] += 0.5f * noobj * fminf(xo[a] + l, 100.0f);   // bce(p,0)
        }
        vals[4] += noobj;
    }

    // --- block reduction (5 channels) ---
    #pragma unroll
    for (int off = 16; off > 0; off >>= 1) {
        #pragma unroll
        for (int j = 0; j < 5; j++)
            vals[j] += __shfl_down_sync(0xFFFFFFFFu, vals[j], off);
    }
    if (lane == 0) {
        #pragma unroll
        for (int j = 0; j < 5; j++) s_red[warp][j] = vals[j];
    }
    __syncthreads();
    if (warp == 0) {
        float r[5];
        #pragma unroll
        for (int j = 0; j < 5; j++) r[j] = (lane < 8) ? s_red[lane][j] : 0.0f;
        #pragma unroll
        for (int off = 4; off > 0; off >>= 1) {
            #pragma unroll
            for (int j = 0; j < 5; j++)
                r[j] += __shfl_down_sync(0xFFFFFFFFu, r[j], off);
        }
        if (lane == 0) {
            #pragma unroll
            for (int j = 0; j < 5; j++) atomicAdd(&g_acc[j], (double)r[j]);
            __threadfence();
            const int old = atomicAdd(&g_count, 1);
            if (old == TOTAL_BLOCKS - 1) s_isLast = 1;
        }
    }
    __syncthreads();

    // --- last block, thread 0: finalize + reset for next replay ---
    if (s_isLast && tid == 0) {
        const double s0 = g_acc[0], s1 = g_acc[1], s2 = g_acc[2];
        const double npos = g_acc[3], s4 = g_acc[4];
        const double box_loss  = 0.05 * s0 / npos;
        const double grid_loss = s1 / (npos + s4) + 0.5 * s2 / (npos * (double)NCLS);
        out[0] = (float)box_loss;
        out[1] = (float)grid_loss;
        #pragma unroll
        for (int j = 0; j < 5; j++) g_acc[j] = 0.0;
        g_count = 0;
    }
}

extern "C" void kernel_launch(void* const* d_in, const int* in_sizes, int n_in,
                              void* d_out, int out_size) {
    const float* head    = (const float*)d_in[0];
    const float* boxes   = (const float*)d_in[1];
    const float* anchors = (const float*)d_in[2];
    const int*   labels  = (const int*)d_in[3];
    (void)in_sizes; (void)n_in; (void)out_size;

    dim3 grid(TILES, BATCH);
    yolo_fused_kernel<<<grid, THREADS>>>(head, boxes, anchors, labels, (float*)d_out);
}

// round 7
// speedup vs baseline: 1.6238x; 1.0039x over previous
#include <cuda_runtime.h>

// Problem constants (fixed by the dataset)
#define BATCH 32
#define NA    3
#define GH    80
#define GW    80
#define NB    50
#define NCLS  1
#define HW    (GH*GW)                 // 6400
#define THREADS 256

// 16x16 spatial tiles; one block = one tile x ALL 3 anchors (768 cells, 3/thread)
#define TW 16
#define TH 16
#define TILES_X (GW/TW)               // 5
#define TILES_Y (GH/TH)               // 5
#define TILES   (TILES_X*TILES_Y)     // 25
#define TOTAL_BLOCKS (BATCH*TILES)    // 800

// Global accumulators: box, weighted_obj, cls, n_pos, noobj_cnt
__device__ double g_acc[5] = {0.0, 0.0, 0.0, 0.0, 0.0};
__device__ int    g_count  = 0;

__device__ __forceinline__ float tanh_fast(float x) {
    float t;
    asm("tanh.approx.f32 %0, %1;" : "=f"(t) : "f"(x));
    return t;
}

__global__ __launch_bounds__(THREADS, 6) void yolo_fused_kernel(
    const float* __restrict__ head,
    const float* __restrict__ boxes,
    const float* __restrict__ anchors,
    const int*   __restrict__ labels,
    float* __restrict__ out)
{
    __shared__ float4 s_cxyxy[64];   // pruned GT xyxy, two 32-wide segments
    __shared__ float  s_caG3[64];    // pruned GT area/3
    __shared__ int    s_pcnt[2];
    __shared__ int    s_mpk[64];     // match candidate packed (anc<<22)|(gj<<14)|(gi<<6)|n
    __shared__ int    s_mcnt[2];
    __shared__ float4 s_box[NB];     // (cx, cy, w, h) all gts
    __shared__ float4 s_xyxy[NB];    // xyxy all gts
    __shared__ int    s_lab[NB];
    __shared__ float  s_red[8][5];

    const int b    = blockIdx.y;
    const int t    = blockIdx.x;                 // 0..24 spatial tile
    const int tid  = threadIdx.x;
    const int th   = t / TILES_X;
    const int tw   = t - th * TILES_X;
    const int w0   = tw * TW;
    const int h0   = th * TH;
    const int lane = tid & 31, warp = tid >> 5;

    // --- issue ALL head loads first (MLP 15, overlaps GT prep below) ---
    const int wx    = w0 + (tid & (TW-1));
    const int hy    = h0 + (tid >> 4);
    const int rem   = hy * GW + wx;
    const int base0 = (b * NA) * (6 * HW) + rem;     // fits in int32

    float xo[NA], hx[NA], hyv[NA], hw[NA], hh[NA];
    #pragma unroll
    for (int a = 0; a < NA; a++) {
        const int base = base0 + a * (6 * HW);
        xo[a]  = head[base];
        hx[a]  = head[base +     HW];
        hyv[a] = head[base + 2 * HW];
        hw[a]  = head[base + 3 * HW];
        hh[a]  = head[base + 4 * HW];
    }

    // --- per-GT prep: warps 0-1, ballot compaction (overlaps head-load latency) ---
    if (tid < 64) {
        const bool valid = tid < NB;
        float4 g = valid ? ((const float4*)boxes)[b * NB + tid]
                         : make_float4(4.0f, 4.0f, 0.0f, 0.0f);
        const float cx = g.x, cy = g.y, w = g.z, h = g.w;
        const int gi = (int)floorf(cx * (float)GW);
        const int gj = (int)floorf(cy * (float)GH);
        const float aG = w * h;
        // anchor argmax (first max wins, matching jnp.argmax)
        int anc = 0; float best = -1.0f;
        #pragma unroll
        for (int k = 0; k < NA; k++) {
            const float aw = anchors[2*k], ah = anchors[2*k+1];
            const float it = fminf(w, aw) * fminf(h, ah);
            const float un = aG + aw * ah - it;
            const float r  = it / un;
            if (r > best) { best = r; anc = k; }
        }
        const float x1 = cx - 0.5f*w, y1 = cy - 0.5f*h;
        const float x2 = cx + 0.5f*w, y2 = cy + 0.5f*h;
        if (valid) {
            s_box[tid]  = g;
            s_xyxy[tid] = make_float4(x1, y1, x2, y2);
            s_lab[tid]  = labels[b * NB + tid];
        }
        // match candidates (segment = warp), packed single word
        const bool mpred = valid && gi >= w0 && gi < w0 + TW && gj >= h0 && gj < h0 + TH;
        const unsigned mb = __ballot_sync(0xFFFFFFFFu, mpred);
        if (mpred) {
            const int pos = warp * 32 + __popc(mb & ((1u << lane) - 1u));
            s_mpk[pos] = (anc << 22) | (gj << 14) | (gi << 6) | tid;
        }
        if (lane == 0) s_mcnt[warp] = __popc(mb);
        // noobj prune: iou>0.5 requires pred center strictly inside gt box.
        const float bxLo = ((float)w0        - 0.1f) * (1.0f/GW) - 1e-4f;
        const float bxHi = ((float)(w0+TW-1) + 1.1f) * (1.0f/GW) + 1e-4f;
        const float byLo = ((float)h0        - 0.1f) * (1.0f/GH) - 1e-4f;
        const float byHi = ((float)(h0+TH-1) + 1.1f) * (1.0f/GH) + 1e-4f;
        const bool ppred = valid && x1 < bxHi && x2 > bxLo && y1 < byHi && y2 > byLo;
        const unsigned pb = __ballot_sync(0xFFFFFFFFu, ppred);
        if (ppred) {
            const int pos = warp * 32 + __popc(pb & ((1u << lane) - 1u));
            s_cxyxy[pos] = make_float4(x1, y1, x2, y2);
            s_caG3[pos]  = aG * (1.0f/3.0f);
        }
        if (lane == 0) s_pcnt[warp] = __popc(pb);
    }

    // --- decode pred boxes: leaky-sigmoid via tanh (1.2*sig(x)-0.1 = 0.6*tanh(x/2)+0.5) ---
    float px1[NA], py1[NA], px2[NA], py2[NA], aP3[NA];
    #pragma unroll
    for (int a = 0; a < NA; a++) {
        const float tx = tanh_fast(0.5f * hx[a]);
        const float ty = tanh_fast(0.5f * hyv[a]);
        const float bx = (0.6f * tx + 0.5f + (float)wx) * (1.0f/GW);
        const float by = (0.6f * ty + 0.5f + (float)hy) * (1.0f/GH);
        const float bw = __expf(hw[a]) * anchors[2*a];
        const float bh = __expf(hh[a]) * anchors[2*a+1];
        px1[a] = bx - 0.5f*bw; py1[a] = by - 0.5f*bh;
        px2[a] = bx + 0.5f*bw; py2[a] = by + 0.5f*bh;
        aP3[a] = bw * bh * (1.0f/3.0f);
    }
    __syncthreads();

    // --- noobj scan: GT outer, anchors inner, warp-uniform y refinement ---
    const int   wrow = h0 + ((tid >> 5) << 1);
    const float wyLo = ((float)wrow        - 0.1f) * (1.0f/GH) - 1e-4f;
    const float wyHi = ((float)(wrow + 1)  + 1.1f) * (1.0f/GH) + 1e-4f;
    bool ign[NA] = {false, false, false};
    #pragma unroll
    for (int s = 0; s < 2; s++) {
        const int c = s_pcnt[s];
        for (int k = 0; k < c; k++) {
            const float4 g = s_cxyxy[s*32 + k];          // broadcast LDS
            if (g.y < wyHi && g.w > wyLo) {              // warp-uniform branch
                const float aG3 = s_caG3[s*32 + k];
                #pragma unroll
                for (int a = 0; a < NA; a++) {
                    const float ox = fminf(px2[a], g.z) - fmaxf(px1[a], g.x);
                    const float oy = fminf(py2[a], g.w) - fmaxf(py1[a], g.y);
                    ign[a] = ign[a] ||
                        (fmaxf(ox, 0.0f) * fmaxf(oy, 0.0f) > aG3 + aP3[a]);
                }
            }
        }
    }

    // --- single match scan for all 3 anchors (last-write-wins == max n) ---
    int bestA[NA] = {-1, -1, -1};
    {
        const int ij = (hy << 8) | wx;
        #pragma unroll
        for (int s = 0; s < 2; s++) {
            const int c = s_mcnt[s];
            for (int k = 0; k < c; k++) {
                const int pk = s_mpk[s*32 + k];
                if (((pk >> 6) & 0xFFFF) == ij) {
                    const int anc = pk >> 22;
                    const int n   = pk & 63;
                    if (anc == 0)      bestA[0] = max(bestA[0], n);
                    else if (anc == 1) bestA[1] = max(bestA[1], n);
                    else               bestA[2] = max(bestA[2], n);
                }
            }
        }
    }

    // --- per-anchor accumulation (5 pre-weighted channels) ---
    // c0=box, c1=1.5*obj+0.5*noobj_bce, c2=cls, c3=n_pos, c4=noobj_cnt
    float vals[5] = {0.0f, 0.0f, 0.0f, 0.0f, 0.0f};
    #pragma unroll
    for (int a = 0; a < NA; a++) {
        const float noobj = ign[a] ? 0.0f : 1.0f;
        const int bestN = bestA[a];

        // softplus: -log(sigmoid(x)) = log(1+e^-x); -log(1-sigmoid(x)) = x + log(1+e^-x)
        const float l = __logf(1.0f + __expf(-xo[a]));

        if (bestN >= 0) {
            vals[3] += 1.0f;                     // n_pos
            const float bceP1 = fminf(l, 100.0f);
            vals[1] += 1.5f * bceP1 + 0.5f * noobj * bceP1;
            // cls bce (lazy load + exp-based sigmoid for log accuracy)
            const float xCls = head[base0 + a * (6 * HW) + 5 * HW];
            const float pCls = __fdividef(1.0f, 1.0f + __expf(-xCls));
            const float tC   = (s_lab[bestN] == 0) ? 1.0f : 0.0f;
            const float lc1  = fmaxf(__logf(pCls),        -100.0f);
            const float lc0  = fmaxf(__logf(1.0f - pCls), -100.0f);
            vals[2] += -(tC * lc1 + (1.0f - tC) * lc0);
            // ciou(pred, target); recover bx,by,bw,bh from extents
            const float bw = px2[a] - px1[a], bh = py2[a] - py1[a];
            const float bx = 0.5f * (px1[a] + px2[a]);
            const float by = 0.5f * (py1[a] + py2[a]);
            const float4 gb = s_box[bestN];
            const float4 gx = s_xyxy[bestN];
            const float imx = fmaxf(px1[a], gx.x), imy = fmaxf(py1[a], gx.y);
            const float iMx = fminf(px2[a], gx.z), iMy = fminf(py2[a], gx.w);
            const float iw = fmaxf(iMx - imx, 0.0f), ihh = fmaxf(iMy - imy, 0.0f);
            const float inter = iw * ihh;
            const float uni = bw * bh + gb.z * gb.w - inter;
            const float iou = inter / fmaxf(uni, 1e-6f);
            const float d   = fabsf(bx - gb.x) + fabsf(by - gb.y);
            const float ex1 = fminf(px1[a], gx.x), ey1 = fminf(py1[a], gx.y);
            const float ex2 = fmaxf(px2[a], gx.z), ey2 = fmaxf(py2[a], gx.w);
            const float cc  = fabsf(ex2 - ex1) + fabsf(ey2 - ey1);
            const float dis = d / fmaxf(cc, 1e-6f);
            const float a1  = atanf(bw / fmaxf(bh, 1e-6f));
            const float a2  = atanf(gb.z / fmaxf(gb.w, 1e-6f));
            const float PIc = 3.1415926f;
            const float vv  = (4.0f / (PIc * PIc)) * fabsf(a1 - a2);
            const float al  = vv / fmaxf(1.0f - iou + vv, 1e-6f);
            vals[0] += 1.0f - iou + dis + al * vv;
        } else {
            vals[1] += 0.5f * noobj * fminf(xo[a] + l, 100.0f);   // bce(p,0)
        }
        vals[4] += noobj;
    }

    // --- block reduction (5 channels) ---
    #pragma unroll
    for (int off = 16; off > 0; off >>= 1) {
        #pragma unroll
        for (int j = 0; j < 5; j++)
            vals[j] += __shfl_down_sync(0xFFFFFFFFu, vals[j], off);
    }
    if (lane == 0) {
        #pragma unroll
        for (int j = 0; j < 5; j++) s_red[warp][j] = vals[j];
    }
    __syncthreads();
    if (warp == 0) {
        float r[5];
        #pragma unroll
        for (int j = 0; j < 5; j++) r[j] = (lane < 8) ? s_red[lane][j] : 0.0f;
        #pragma unroll
        for (int off = 4; off > 0; off >>= 1) {
            #pragma unroll
            for (int j = 0; j < 5; j++)
                r[j] += __shfl_down_sync(0xFFFFFFFFu, r[j], off);
        }
        if (lane == 0) {
            #pragma unroll
            for (int j = 0; j < 5; j++) atomicAdd(&g_acc[j], (double)r[j]);
            __threadfence();
            const int old = atomicAdd(&g_count, 1);
            if (old == TOTAL_BLOCKS - 1) {
                // last block: all prior blocks' adds are fenced before their
                // g_count increment; fence again before reading.
                __threadfence();
                const double s0 = g_acc[0], s1 = g_acc[1], s2 = g_acc[2];
                const double npos = g_acc[3], s4 = g_acc[4];
                out[0] = (float)(0.05 * s0 / npos);
                out[1] = (float)(s1 / (npos + s4) + 0.5 * s2 / (npos * (double)NCLS));
                #pragma unroll
                for (int j = 0; j < 5; j++) g_acc[j] = 0.0;
                g_count = 0;   // reset for next graph replay
            }
        }
    }
}

extern "C" void kernel_launch(void* const* d_in, const int* in_sizes, int n_in,
                              void* d_out, int out_size) {
    const float* head    = (const float*)d_in[0];
    const float* boxes   = (const float*)d_in[1];
    const float* anchors = (const float*)d_in[2];
    const int*   labels  = (const int*)d_in[3];
    (void)in_sizes; (void)n_in; (void)out_size;

    dim3 grid(TILES, BATCH);
    yolo_fused_kernel<<<grid, THREADS>>>(head, boxes, anchors, labels, (float*)d_out);
}